// round 10
// baseline (speedup 1.0000x reference)
#include <cuda_runtime.h>

// LatentReverb fused single-kernel v5 (= proven R8 v3 + hoisted per-iter scalars)
// B=4, C=4, H=W=64, NREF=16; DECAY=0.8, WET_MIX=0.3, FEEDBACK=0.4, ROOM=0.5
// Primary:  grid (16,4), cluster 16 (nonportable), 512 thr/CTA, 4 rows/CTA.
// Fallback: grid (8,4),  cluster 8,               1024 thr/CTA, 8 rows/CTA.

#define LOG2E 1.4426950408889634f

// ---------------- scratch (static device globals; no allocation) -------------
__device__ float4 g_fb[2][4*4096];   // ping-pong feedback state (channel-last)
__device__ float4 g_x4  [4*4096];    // x transposed to channel-last
__device__ float4 g_q4  [4*4096];    // per-pixel q (4 heads)
__device__ float2 g_kv  [16*4096];   // per (b,h): (k, v)
__device__ float  g_red [4][16][16]; // per (b, cta): 16 partial min/max values
__device__ float  g_tab [1024];      // per (b,h): softmax-output table
__device__ float4 g_o4  [4*4096];    // (fallback only)
__device__ float4 g_w34 [4*4096];    // (fallback only)

// ---------------- helpers ----------------------------------------------------
__device__ __forceinline__ float fexp2(float x) {
    float y;
    asm("ex2.approx.ftz.f32 %0, %1;" : "=f"(y) : "f"(x));
    return y;
}
__device__ __forceinline__ float fsig(float x) {
    return __fdividef(1.0f, 1.0f + fexp2(-LOG2E * x));
}
__device__ __forceinline__ float fadef(int i) {
    float v = 1.0f;
    if (i < 4)   v = 0.6f + (0.4f/3.0f) * (float)i;
    if (i >= 60) v = 0.6f + (0.4f/3.0f) * (float)(63 - i);
    return v;
}
__device__ __forceinline__ void csync() {
    asm volatile("barrier.cluster.arrive.aligned;" ::: "memory");
    asm volatile("barrier.cluster.wait.aligned;"   ::: "memory");
}

// =============================================================================
// PRIMARY kernel: cluster 16, 512 threads, 4 rows/CTA, TBL_N=32 span 28
// =============================================================================
__global__ void __launch_bounds__(512, 1) fused16(
    const float* __restrict__ x,
    const float* __restrict__ rw,  const float* __restrict__ rd,
    const float* __restrict__ fw,  const float* __restrict__ fbias,
    const float* __restrict__ d1w, const float* __restrict__ d1b,
    const float* __restrict__ d2w, const float* __restrict__ d2b,
    const float* __restrict__ aiw, const float* __restrict__ aib,
    const float* __restrict__ aow, const float* __restrict__ aob,
    const float* __restrict__ spw, const float* __restrict__ spb,
    const float* __restrict__ ow,  const float* __restrict__ ob,
    float* __restrict__ out)
{
    // unioned scratch:
    //  A: sA f4[0..383] staging, s_part f4[384..639]
    //  C: kv f4[0..2047]
    //  D/E: s_o f4[0..511], s_w34e f4[512..895]
    __shared__ __align__(16) float s_buf[8192];
    __shared__ __align__(16) float s_fw4[144];  // [tap][ic] float4 over oc
    __shared__ float s_cb[4];
    __shared__ float s_d1w[8], s_d1b[2], s_d2w[8], s_d2b[4];
    __shared__ float s_fade[64];
    __shared__ float s_aiw[48], s_aib[12], s_aow[16], s_aob[4];
    __shared__ float s_spw[288], s_spb[8], s_ow[48], s_ob[4];
    __shared__ float s_red[16][16];
    __shared__ float s_meta[16];
    __shared__ float s_tab[128];
    __shared__ int   s_ys[16], s_xs[16], s_ys2[16], s_xs2[16];
    __shared__ float s_wsc[16];

    const int tid  = threadIdx.x;
    const int rank = blockIdx.x;               // cluster rank 0..15
    const int b    = blockIdx.y;

    if (tid < 144) {
        const int oc = tid & 3, ic = (tid >> 2) & 3, tap = tid >> 4;
        s_fw4[tid] = fw[(oc*4 + ic)*9 + tap];
    }
    if (tid < 4)   s_cb[tid]  = fbias[tid];
    if (tid < 8)   s_d1w[tid] = d1w[tid];
    if (tid < 2)   s_d1b[tid] = d1b[tid];
    if (tid < 8)   s_d2w[tid] = d2w[tid];
    if (tid < 4)   s_d2b[tid] = d2b[tid];
    if (tid < 16) {
        // hoisted per-iteration constants (off the phase-A critical path)
        const float dly = rd[tid] * 3.0f;          // exact small int
        s_ys[tid]  = ((int)dly)          & 63;
        s_xs[tid]  = ((int)(2.0f * dly)) & 63;
        s_ys2[tid] = ((int)(dly * 0.5f)) & 63;
        s_xs2[tid] = ((int)dly)          & 63;
        float d = 1.0f;
        #pragma unroll
        for (int i = 0; i < 16; i++) { if (i >= tid) break; d *= 0.8f; }
        s_wsc[tid] = fsig(rw[tid]) * d * 3.0f;
    }
    if (tid < 64)  s_fade[tid] = fadef(tid);
    if (tid < 48)  s_aiw[tid] = aiw[tid];
    if (tid < 12)  s_aib[tid] = aib[tid];
    if (tid < 16)  s_aow[tid] = aow[tid];
    if (tid < 4)   s_aob[tid] = aob[tid];
    {
        int i = tid; if (i < 288) s_spw[i] = spw[i];
        i = tid - 288; if (i >= 0 && i < 8)  s_spb[i] = spb[i];
        i = tid - 296; if (i >= 0 && i < 48) s_ow[i]  = ow[i];
        i = tid - 344; if (i >= 0 && i < 4)  s_ob[i]  = ob[i];
    }

    const bool low  = tid < 256;
    const int  pix  = tid & 255;
    const int  y0   = rank << 2;
    const int  y    = y0 + (pix >> 6);
    const int  xx   = pix & 63;
    const int  off  = (y << 6) + xx;
    const int  pbase = b << 12;

    // ---- init: fb = 0.1*x; x to channel-last -----------------------------
    float fb0 = 0.f, fb1 = 0.f, fb2 = 0.f, fb3 = 0.f;
    float w0 = 0.f, w1 = 0.f, w2 = 0.f, w3 = 0.f;
    if (low) {
        const float x0 = x[((b*4 + 0) << 12) + off];
        const float x1 = x[((b*4 + 1) << 12) + off];
        const float x2 = x[((b*4 + 2) << 12) + off];
        const float x3 = x[((b*4 + 3) << 12) + off];
        __stcg(&g_x4[pbase + off], make_float4(x0, x1, x2, x3));
        fb0 = 0.1f*x0; fb1 = 0.1f*x1; fb2 = 0.1f*x2; fb3 = 0.1f*x3;
        __stcg(&g_fb[0][pbase + off], make_float4(fb0, fb1, fb2, fb3));
    }
    __syncthreads();
    csync();

    // ---- phase A: 16 reflections, one csync each -------------------------
    float4* sA     = (float4*)s_buf;           // 6 rows x 64
    float4* s_part = (float4*)s_buf + 384;
    const float4* fw4 = (const float4*)s_fw4;
    for (int j = 0; j < 16; j++) {
        const int ys = s_ys[j], xs = s_xs[j];
        const int ys2p = (j >= 1) ? s_ys2[j-1] : 0;
        const int xs2p = (j >= 1) ? s_xs2[j-1] : 0;

        const float4* Bp = g_fb[j & 1] + pbase;
        if (tid < 384) {
            const int r = tid >> 6, px = tid & 63;
            const int srow = (y0 - 1 + r - ys) & 63;
            float4 v = __ldcg(&Bp[(srow << 6) + px]);
            if (j >= 2) {
                const float t = 0.08f * s_fade[srow] * s_fade[px];
                const float4 v2 = __ldcg(
                    &Bp[(((srow - ys2p) & 63) << 6) + ((px - xs2p) & 63)]);
                v.x = fmaf(t, v2.x, v.x); v.y = fmaf(t, v2.y, v.y);
                v.z = fmaf(t, v2.z, v.z); v.w = fmaf(t, v2.w, v.w);
            }
            const float fo = s_fade[(y0 - 1 + r) & 63] * s_fade[(px + xs) & 63];
            v.x *= fo; v.y *= fo; v.z *= fo; v.w *= fo;
            sA[tid] = v;
        }
        float fA0 = fb0, fA1 = fb1, fA2 = fb2, fA3 = fb3;
        if (low && j >= 2) {
            const float t = 0.08f * s_fade[y] * s_fade[xx];
            const float4 v2 = __ldcg(
                &Bp[(((y - ys2p) & 63) << 6) + ((xx - xs2p) & 63)]);
            fA0 = fmaf(t, v2.x, fA0); fA1 = fmaf(t, v2.y, fA1);
            fA2 = fmaf(t, v2.z, fA2); fA3 = fmaf(t, v2.w, fA3);
        }
        __syncthreads();

        // tap-split conv3x3
        float r0, r1, r2, r3;
        if (low) { r0 = s_cb[0]; r1 = s_cb[1]; r2 = s_cb[2]; r3 = s_cb[3]; }
        else     { r0 = 0.f; r1 = 0.f; r2 = 0.f; r3 = 0.f; }
        const int rbase = pix >> 6;   // local row 0..3
        #pragma unroll
        for (int t5 = 0; t5 < 5; t5++) {
            int dy, dx;
            if (low) {
                if (t5 == 4) break;
                dy = (t5 < 3) ? -1 : 0;
                dx = (t5 < 3) ? (t5 - 1) : -1;
            } else {
                dy = (t5 < 2) ? 0 : 1;
                dx = (t5 < 2) ? t5 : (t5 - 3);
            }
            const int yy = y + dy, xc = xx + dx;
            if ((unsigned)yy >= 64u || (unsigned)xc >= 64u) continue;
            const float4 v = sA[((rbase + dy + 1) << 6) + ((xc - xs) & 63)];
            const int wt = ((dy + 1)*3 + (dx + 1)) << 2;
            const float4 wa = fw4[wt + 0], wb = fw4[wt + 1];
            const float4 wc = fw4[wt + 2], wd = fw4[wt + 3];
            r0 = fmaf(wa.x, v.x, r0); r1 = fmaf(wa.y, v.x, r1);
            r2 = fmaf(wa.z, v.x, r2); r3 = fmaf(wa.w, v.x, r3);
            r0 = fmaf(wb.x, v.y, r0); r1 = fmaf(wb.y, v.y, r1);
            r2 = fmaf(wb.z, v.y, r2); r3 = fmaf(wb.w, v.y, r3);
            r0 = fmaf(wc.x, v.z, r0); r1 = fmaf(wc.y, v.z, r1);
            r2 = fmaf(wc.z, v.z, r2); r3 = fmaf(wc.w, v.z, r3);
            r0 = fmaf(wd.x, v.w, r0); r1 = fmaf(wd.y, v.w, r1);
            r2 = fmaf(wd.z, v.w, r2); r3 = fmaf(wd.w, v.w, r3);
        }
        if (!low) s_part[pix] = make_float4(r0, r1, r2, r3);
        __syncthreads();

        if (low) {
            const float4 p4 = s_part[pix];
            r0 += p4.x; r1 += p4.y; r2 += p4.z; r3 += p4.w;

            float u0 = s_d1b[0], u1 = s_d1b[1];
            u0 = fmaf(s_d1w[0], r0, u0); u1 = fmaf(s_d1w[4], r0, u1);
            u0 = fmaf(s_d1w[1], r1, u0); u1 = fmaf(s_d1w[5], r1, u1);
            u0 = fmaf(s_d1w[2], r2, u0); u1 = fmaf(s_d1w[6], r2, u1);
            u0 = fmaf(s_d1w[3], r3, u0); u1 = fmaf(s_d1w[7], r3, u1);
            u0 = u0 * fsig(u0);
            u1 = u1 * fsig(u1);
            const float rd0 = r0 * fsig(s_d2b[0] + s_d2w[0]*u0 + s_d2w[1]*u1);
            const float rd1 = r1 * fsig(s_d2b[1] + s_d2w[2]*u0 + s_d2w[3]*u1);
            const float rd2 = r2 * fsig(s_d2b[2] + s_d2w[4]*u0 + s_d2w[5]*u1);
            const float rd3 = r3 * fsig(s_d2b[3] + s_d2w[6]*u0 + s_d2w[7]*u1);

            const float wscale = s_wsc[j];
            w0 = fmaf(rd0, wscale, w0); w1 = fmaf(rd1, wscale, w1);
            w2 = fmaf(rd2, wscale, w2); w3 = fmaf(rd3, wscale, w3);

            if (j < 15) {
                fb0 = fmaf(rd0, 0.24f, fA0); fb1 = fmaf(rd1, 0.24f, fA1);
                fb2 = fmaf(rd2, 0.24f, fA2); fb3 = fmaf(rd3, 0.24f, fA3);
                __stcg(&g_fb[(j + 1) & 1][pbase + off],
                       make_float4(fb0, fb1, fb2, fb3));
            }
        }
        if (j < 15) csync();
    }

    // ---- phase B: qkv + min/max reduction --------------------------------
    if (low) {
        float qh[4], kh[4];
        #pragma unroll
        for (int h = 0; h < 4; h++) {
            float q = s_aib[h], k = s_aib[4 + h], v = s_aib[8 + h];
            q = fmaf(s_aiw[h*4+0],     w0, q); q = fmaf(s_aiw[h*4+1],     w1, q);
            q = fmaf(s_aiw[h*4+2],     w2, q); q = fmaf(s_aiw[h*4+3],     w3, q);
            k = fmaf(s_aiw[(4+h)*4+0], w0, k); k = fmaf(s_aiw[(4+h)*4+1], w1, k);
            k = fmaf(s_aiw[(4+h)*4+2], w2, k); k = fmaf(s_aiw[(4+h)*4+3], w3, k);
            v = fmaf(s_aiw[(8+h)*4+0], w0, v); v = fmaf(s_aiw[(8+h)*4+1], w1, v);
            v = fmaf(s_aiw[(8+h)*4+2], w2, v); v = fmaf(s_aiw[(8+h)*4+3], w3, v);
            qh[h] = q; kh[h] = k;
            __stcg(&g_kv[((b*4 + h) << 12) + off], make_float2(k, v));
        }
        __stcg(&g_q4[pbase + off], make_float4(qh[0], qh[1], qh[2], qh[3]));
        float red[16];
        #pragma unroll
        for (int h = 0; h < 4; h++) {
            red[h] = qh[h]; red[4+h] = qh[h]; red[8+h] = kh[h]; red[12+h] = kh[h];
        }
        #pragma unroll
        for (int o = 16; o > 0; o >>= 1) {
            #pragma unroll
            for (int h = 0; h < 4; h++) {
                red[h]    = fminf(red[h],    __shfl_xor_sync(0xFFFFFFFFu, red[h],    o));
                red[4+h]  = fmaxf(red[4+h],  __shfl_xor_sync(0xFFFFFFFFu, red[4+h],  o));
                red[8+h]  = fminf(red[8+h],  __shfl_xor_sync(0xFFFFFFFFu, red[8+h],  o));
                red[12+h] = fmaxf(red[12+h], __shfl_xor_sync(0xFFFFFFFFu, red[12+h], o));
            }
        }
        if ((tid & 31) == 0) {
            #pragma unroll
            for (int i = 0; i < 16; i++) s_red[tid >> 5][i] = red[i];
        }
    }
    __syncthreads();
    if (tid < 16) {
        const bool ismax = (tid >> 2) & 1;
        float v = s_red[0][tid];
        #pragma unroll
        for (int wq = 1; wq < 8; wq++)
            v = ismax ? fmaxf(v, s_red[wq][tid]) : fminf(v, s_red[wq][tid]);
        g_red[b][rank][tid] = v;
    }
    csync();

    // ---- phase C: softmax table, 32 nodes/head, 8 nodes/CTA --------------
    if (tid < 16) {
        const bool ismax = (tid >> 2) & 1;
        float v = __ldcg(&g_red[b][0][tid]);
        #pragma unroll
        for (int r = 1; r < 16; r++) {
            const float u = __ldcg(&g_red[b][r][tid]);
            v = ismax ? fmaxf(v, u) : fminf(v, u);
        }
        s_meta[tid] = v;
    }
    {
        const int head = rank >> 2;
        float4*       dst = (float4*)s_buf;
        const float4* src = (const float4*)&g_kv[((b*4 + head) << 12)];
        #pragma unroll
        for (int k4 = 0; k4 < 4; k4++)
            dst[tid + (k4 << 9)] = __ldcg(&src[tid + (k4 << 9)]);
        __syncthreads();

        const float amin = s_meta[head],     amax = s_meta[4 + head];
        const float kmn  = s_meta[8 + head], kmx  = s_meta[12 + head];
        const float hs   = fmaxf((amax - amin) * (1.0f/28.0f), 1e-30f);
        const int   nloc = tid >> 6;                 // 0..7
        const int   l64  = tid & 63;
        const int   n    = ((rank & 3) << 3) + nloc; // 0..31
        const float a2   = (amin + (float)(n - 1) * hs) * LOG2E;
        const float m2   = fmaxf(a2 * kmn, a2 * kmx);

        float num = 0.f, den = 0.f;
        const float2* p2 = (const float2*)s_buf;
        #pragma unroll 8
        for (int jj = 0; jj < 64; jj++) {
            const float2 kv = p2[l64 + (jj << 6)];
            const float  e  = fexp2(fmaf(a2, kv.x, -m2));
            num = fmaf(e, kv.y, num);
            den += e;
        }
        #pragma unroll
        for (int o = 16; o > 0; o >>= 1) {
            num += __shfl_xor_sync(0xFFFFFFFFu, num, o);
            den += __shfl_xor_sync(0xFFFFFFFFu, den, o);
        }
        if ((tid & 31) == 0) {
            s_red[tid >> 5][0] = num;
            s_red[tid >> 5][1] = den;
        }
        __syncthreads();
        if (tid < 8) {
            const float nm = s_red[2*tid][0] + s_red[2*tid + 1][0];
            const float dn = s_red[2*tid][1] + s_red[2*tid + 1][1];
            __stcg(&g_tab[(b*4 + head)*32 + ((rank & 3) << 3) + tid],
                   __fdividef(nm, dn));
        }
    }
    csync();

    // ---- phase D: interp o for 8 rows (own 4 + 2-row halos) into SMEM ----
    if (tid < 128) s_tab[tid] = __ldcg(&g_tab[b*128 + tid]);
    __syncthreads();
    float4* s_o = (float4*)s_buf;              // [8][64]
    {
        const int erow = tid >> 6, col = tid & 63;
        const int ry   = y0 - 2 + erow;
        float4 ov = make_float4(0.f, 0.f, 0.f, 0.f);
        if ((unsigned)ry < 64u) {
            const float4 q4 = __ldcg(&g_q4[pbase + (ry << 6) + col]);
            const float qa[4] = { q4.x, q4.y, q4.z, q4.w };
            float oh[4];
            #pragma unroll
            for (int h = 0; h < 4; h++) {
                const float amin = s_meta[h];
                const float hs = fmaxf((s_meta[4+h] - amin)*(1.0f/28.0f), 1e-30f);
                float sr = (qa[h] - amin) * __fdividef(1.0f, hs);
                sr = fminf(fmaxf(sr, 0.0f), 28.0f);
                const float fi = floorf(sr);
                const int   i0 = (int)fi;
                const float f  = sr - fi;
                const float* t = &s_tab[(h << 5) + i0];
                const float fm1 = f + 1.0f, f1 = f - 1.0f, f2 = f - 2.0f;
                const float c0 = -f  * f1 * f2 * (1.0f/6.0f);
                const float c1 =  fm1 * f1 * f2 * 0.5f;
                const float c2 = -fm1 * f  * f2 * 0.5f;
                const float c3 =  fm1 * f  * f1 * (1.0f/6.0f);
                oh[h] = c0*t[0] + c1*t[1] + c2*t[2] + c3*t[3];
            }
            ov = make_float4(oh[0], oh[1], oh[2], oh[3]);
        }
        s_o[tid] = ov;
    }
    __syncthreads();

    // ---- phase E1: box blur + attn out-projection for 6 rows into SMEM ---
    float4* s_w34e = (float4*)s_buf + 512;     // [6][64]
    if (tid < 384) {
        const int brow = tid >> 6, col = tid & 63;
        const int row  = y0 - 1 + brow;
        if ((unsigned)row < 64u) {
            float sx = 0.f, sy = 0.f, sz = 0.f, sw = 0.f, cnt = 0.f;
            #pragma unroll
            for (int dy = -1; dy <= 1; dy++) {
                const int r2 = row + dy;
                if ((unsigned)r2 >= 64u) continue;
                const int er = brow + 1 + dy;
                #pragma unroll
                for (int dx = -1; dx <= 1; dx++) {
                    const int c2 = col + dx;
                    if ((unsigned)c2 >= 64u) continue;
                    const float4 o = s_o[(er << 6) + c2];
                    sx += o.x; sy += o.y; sz += o.z; sw += o.w;
                    cnt += 1.0f;
                }
            }
            float oc[4];
            #pragma unroll
            for (int c = 0; c < 4; c++) {
                float pr = cnt * s_aob[c];
                pr = fmaf(s_aow[c*4+0], sx, pr); pr = fmaf(s_aow[c*4+1], sy, pr);
                pr = fmaf(s_aow[c*4+2], sz, pr); pr = fmaf(s_aow[c*4+3], sw, pr);
                oc[c] = pr * (1.0f/9.0f);
            }
            s_w34e[tid] = make_float4(oc[0], oc[1], oc[2], oc[3]);
        }
    }
    __syncthreads();

    // ---- phase E2: edge enhance + spatial conv + 1x1 out + mix -----------
    if (low) {
        const int lrow = pix >> 6;
        const float4 ctr = s_w34e[((lrow + 1) << 6) + xx];
        float n0 = 0.f, n1 = 0.f, n2 = 0.f, n3 = 0.f;
        float sf[8];
        float4 xctr = make_float4(0.f, 0.f, 0.f, 0.f);
        #pragma unroll
        for (int o = 0; o < 8; o++) sf[o] = s_spb[o];
        #pragma unroll
        for (int dy = -1; dy <= 1; dy++) {
            const int yy = y + dy;
            if ((unsigned)yy >= 64u) continue;
            const int wr = lrow + 1 + dy;
            #pragma unroll
            for (int dx = -1; dx <= 1; dx++) {
                const int xc = xx + dx;
                if ((unsigned)xc >= 64u) continue;
                if (!(dy == 0 && dx == 0)) {
                    const float4 v = s_w34e[(wr << 6) + xc];
                    n0 += v.x; n1 += v.y; n2 += v.z; n3 += v.w;
                }
                const float4 xv = __ldcg(&g_x4[pbase + (yy << 6) + xc]);
                if (dy == 0 && dx == 0) xctr = xv;
                const int wtap = (dy + 1)*3 + (dx + 1);
                #pragma unroll
                for (int o = 0; o < 8; o++) {
                    float a = sf[o];
                    a = fmaf(s_spw[(o*4 + 0)*9 + wtap], xv.x, a);
                    a = fmaf(s_spw[(o*4 + 1)*9 + wtap], xv.y, a);
                    a = fmaf(s_spw[(o*4 + 2)*9 + wtap], xv.z, a);
                    a = fmaf(s_spw[(o*4 + 3)*9 + wtap], xv.w, a);
                    sf[o] = a;
                }
            }
        }
        float wet4[4];
        wet4[0] = fmaf(8.0f*ctr.x - n0, 0.04f, ctr.x);
        wet4[1] = fmaf(8.0f*ctr.y - n1, 0.04f, ctr.y);
        wet4[2] = fmaf(8.0f*ctr.z - n2, 0.04f, ctr.z);
        wet4[3] = fmaf(8.0f*ctr.w - n3, 0.04f, ctr.w);

        const float xc4[4] = { xctr.x, xctr.y, xctr.z, xctr.w };
        #pragma unroll
        for (int c = 0; c < 4; c++) {
            float pr = s_ob[c];
            #pragma unroll
            for (int jq = 0; jq < 8; jq++) pr = fmaf(s_ow[c*12 + jq],     sf[jq],   pr);
            #pragma unroll
            for (int jq = 0; jq < 4; jq++) pr = fmaf(s_ow[c*12 + 8 + jq], wet4[jq], pr);
            out[((b*4 + c) << 12) + off] = fmaf(xc4[c], 0.7f, 0.3f * pr);
        }
    }
}

// =============================================================================
// FALLBACK kernel: proven config (cluster 8, 1024 thr, TBL 64 span 60)
// =============================================================================
__global__ void __cluster_dims__(8,1,1) __launch_bounds__(1024, 1) fused8(
    const float* __restrict__ x,
    const float* __restrict__ rw,  const float* __restrict__ rd,
    const float* __restrict__ fw,  const float* __restrict__ fbias,
    const float* __restrict__ d1w, const float* __restrict__ d1b,
    const float* __restrict__ d2w, const float* __restrict__ d2b,
    const float* __restrict__ aiw, const float* __restrict__ aib,
    const float* __restrict__ aow, const float* __restrict__ aob,
    const float* __restrict__ spw, const float* __restrict__ spb,
    const float* __restrict__ ow,  const float* __restrict__ ob,
    float* __restrict__ out)
{
    __shared__ __align__(16) float s_buf[8192];
    __shared__ __align__(16) float s_fw4[144];
    __shared__ float s_cb[4];
    __shared__ float s_d1w[8], s_d1b[2], s_d2w[8], s_d2b[4];
    __shared__ float s_rw[16], s_rd[16], s_fade[64];
    __shared__ float s_aiw[48], s_aib[12], s_aow[16], s_aob[4];
    __shared__ float s_spw[288], s_spb[8], s_ow[48], s_ob[4];
    __shared__ float s_red[16][16];
    __shared__ float s_meta[16];

    const int tid  = threadIdx.x;
    const int rank = blockIdx.x;
    const int b    = blockIdx.y;

    if (tid < 144) {
        const int oc = tid & 3, ic = (tid >> 2) & 3, tap = tid >> 4;
        s_fw4[tid] = fw[(oc*4 + ic)*9 + tap];
    }
    if (tid < 4)   s_cb[tid]  = fbias[tid];
    if (tid < 8)   s_d1w[tid] = d1w[tid];
    if (tid < 2)   s_d1b[tid] = d1b[tid];
    if (tid < 8)   s_d2w[tid] = d2w[tid];
    if (tid < 4)   s_d2b[tid] = d2b[tid];
    if (tid < 16)  { s_rw[tid] = rw[tid]; s_rd[tid] = rd[tid]; }
    if (tid < 64)  s_fade[tid] = fadef(tid);
    if (tid < 48)  s_aiw[tid] = aiw[tid];
    if (tid < 12)  s_aib[tid] = aib[tid];
    if (tid < 16)  s_aow[tid] = aow[tid];
    if (tid < 4)   s_aob[tid] = aob[tid];
    {
        int i = tid; if (i < 288) s_spw[i] = spw[i];
        i = tid - 288; if (i >= 0 && i < 8)  s_spb[i] = spb[i];
        i = tid - 296; if (i >= 0 && i < 48) s_ow[i]  = ow[i];
        i = tid - 344; if (i >= 0 && i < 4)  s_ob[i]  = ob[i];
    }

    const bool low  = tid < 512;
    const int  pix  = tid & 511;
    const int  y0   = rank << 3;
    const int  y    = y0 + (pix >> 6);
    const int  xx   = pix & 63;
    const int  off  = (y << 6) + xx;
    const int  pbase = b << 12;

    float fb0 = 0.f, fb1 = 0.f, fb2 = 0.f, fb3 = 0.f;
    float w0 = 0.f, w1 = 0.f, w2 = 0.f, w3 = 0.f;
    if (low) {
        const float x0 = x[((b*4 + 0) << 12) + off];
        const float x1 = x[((b*4 + 1) << 12) + off];
        const float x2 = x[((b*4 + 2) << 12) + off];
        const float x3 = x[((b*4 + 3) << 12) + off];
        __stcg(&g_x4[pbase + off], make_float4(x0, x1, x2, x3));
        fb0 = 0.1f*x0; fb1 = 0.1f*x1; fb2 = 0.1f*x2; fb3 = 0.1f*x3;
        __stcg(&g_fb[0][pbase + off], make_float4(fb0, fb1, fb2, fb3));
    }
    __syncthreads();
    csync();

    float4* sA     = (float4*)s_buf;
    float4* s_part = (float4*)s_buf + 768;
    const float4* fw4 = (const float4*)s_fw4;
    float decay = 1.0f;
    int ys2p = 0, xs2p = 0;
    for (int j = 0; j < 16; j++) {
        const float dly = s_rd[j] * 3.0f;
        const int ys = ((int)dly)          & 63;
        const int xs = ((int)(2.0f * dly)) & 63;

        const float4* Bp = g_fb[j & 1] + pbase;
        if (tid < 640) {
            const int r = tid >> 6, px = tid & 63;
            const int srow = (y0 - 1 + r - ys) & 63;
            float4 v = __ldcg(&Bp[(srow << 6) + px]);
            if (j >= 2) {
                const float t = 0.08f * s_fade[srow] * s_fade[px];
                const float4 v2 = __ldcg(
                    &Bp[(((srow - ys2p) & 63) << 6) + ((px - xs2p) & 63)]);
                v.x = fmaf(t, v2.x, v.x); v.y = fmaf(t, v2.y, v.y);
                v.z = fmaf(t, v2.z, v.z); v.w = fmaf(t, v2.w, v.w);
            }
            const float fo = s_fade[(y0 - 1 + r) & 63] * s_fade[(px + xs) & 63];
            v.x *= fo; v.y *= fo; v.z *= fo; v.w *= fo;
            sA[tid] = v;
        }
        float fA0 = fb0, fA1 = fb1, fA2 = fb2, fA3 = fb3;
        if (low && j >= 2) {
            const float t = 0.08f * s_fade[y] * s_fade[xx];
            const float4 v2 = __ldcg(
                &Bp[(((y - ys2p) & 63) << 6) + ((xx - xs2p) & 63)]);
            fA0 = fmaf(t, v2.x, fA0); fA1 = fmaf(t, v2.y, fA1);
            fA2 = fmaf(t, v2.z, fA2); fA3 = fmaf(t, v2.w, fA3);
        }
        __syncthreads();

        float r0, r1, r2, r3;
        if (low) { r0 = s_cb[0]; r1 = s_cb[1]; r2 = s_cb[2]; r3 = s_cb[3]; }
        else     { r0 = 0.f; r1 = 0.f; r2 = 0.f; r3 = 0.f; }
        const int rbase = pix >> 6;
        #pragma unroll
        for (int t5 = 0; t5 < 5; t5++) {
            int dy, dx;
            if (low) {
                if (t5 == 4) break;
                dy = (t5 < 3) ? -1 : 0;
                dx = (t5 < 3) ? (t5 - 1) : -1;
            } else {
                dy = (t5 < 2) ? 0 : 1;
                dx = (t5 < 2) ? t5 : (t5 - 3);
            }
            const int yy = y + dy, xc = xx + dx;
            if ((unsigned)yy >= 64u || (unsigned)xc >= 64u) continue;
            const float4 v = sA[((rbase + dy + 1) << 6) + ((xc - xs) & 63)];
            const int wt = ((dy + 1)*3 + (dx + 1)) << 2;
            const float4 wa = fw4[wt + 0], wb = fw4[wt + 1];
            const float4 wc = fw4[wt + 2], wd = fw4[wt + 3];
            r0 = fmaf(wa.x, v.x, r0); r1 = fmaf(wa.y, v.x, r1);
            r2 = fmaf(wa.z, v.x, r2); r3 = fmaf(wa.w, v.x, r3);
            r0 = fmaf(wb.x, v.y, r0); r1 = fmaf(wb.y, v.y, r1);
            r2 = fmaf(wb.z, v.y, r2); r3 = fmaf(wb.w, v.y, r3);
            r0 = fmaf(wc.x, v.z, r0); r1 = fmaf(wc.y, v.z, r1);
            r2 = fmaf(wc.z, v.z, r2); r3 = fmaf(wc.w, v.z, r3);
            r0 = fmaf(wd.x, v.w, r0); r1 = fmaf(wd.y, v.w, r1);
            r2 = fmaf(wd.z, v.w, r2); r3 = fmaf(wd.w, v.w, r3);
        }
        if (!low) s_part[pix] = make_float4(r0, r1, r2, r3);
        __syncthreads();

        if (low) {
            const float4 p4 = s_part[pix];
            r0 += p4.x; r1 += p4.y; r2 += p4.z; r3 += p4.w;

            float u0 = s_d1b[0], u1 = s_d1b[1];
            u0 = fmaf(s_d1w[0], r0, u0); u1 = fmaf(s_d1w[4], r0, u1);
            u0 = fmaf(s_d1w[1], r1, u0); u1 = fmaf(s_d1w[5], r1, u1);
            u0 = fmaf(s_d1w[2], r2, u0); u1 = fmaf(s_d1w[6], r2, u1);
            u0 = fmaf(s_d1w[3], r3, u0); u1 = fmaf(s_d1w[7], r3, u1);
            u0 = u0 * fsig(u0);
            u1 = u1 * fsig(u1);
            const float rd0 = r0 * fsig(s_d2b[0] + s_d2w[0]*u0 + s_d2w[1]*u1);
            const float rd1 = r1 * fsig(s_d2b[1] + s_d2w[2]*u0 + s_d2w[3]*u1);
            const float rd2 = r2 * fsig(s_d2b[2] + s_d2w[4]*u0 + s_d2w[5]*u1);
            const float rd3 = r3 * fsig(s_d2b[3] + s_d2w[6]*u0 + s_d2w[7]*u1);

            const float wscale = fsig(s_rw[j]) * decay * 3.0f;
            w0 = fmaf(rd0, wscale, w0); w1 = fmaf(rd1, wscale, w1);
            w2 = fmaf(rd2, wscale, w2); w3 = fmaf(rd3, wscale, w3);

            if (j < 15) {
                fb0 = fmaf(rd0, 0.24f, fA0); fb1 = fmaf(rd1, 0.24f, fA1);
                fb2 = fmaf(rd2, 0.24f, fA2); fb3 = fmaf(rd3, 0.24f, fA3);
                __stcg(&g_fb[(j + 1) & 1][pbase + off],
                       make_float4(fb0, fb1, fb2, fb3));
            }
        }
        ys2p = ((int)(dly * 0.5f)) & 63;
        xs2p = ((int)dly)          & 63;
        decay *= 0.8f;
        if (j < 15) csync();
    }

    if (low) {
        float qh[4], kh[4];
        #pragma unroll
        for (int h = 0; h < 4; h++) {
            float q = s_aib[h], k = s_aib[4 + h], v = s_aib[8 + h];
            q = fmaf(s_aiw[h*4+0],     w0, q); q = fmaf(s_aiw[h*4+1],     w1, q);
            q = fmaf(s_aiw[h*4+2],     w2, q); q = fmaf(s_aiw[h*4+3],     w3, q);
            k = fmaf(s_aiw[(4+h)*4+0], w0, k); k = fmaf(s_aiw[(4+h)*4+1], w1, k);
            k = fmaf(s_aiw[(4+h)*4+2], w2, k); k = fmaf(s_aiw[(4+h)*4+3], w3, k);
            v = fmaf(s_aiw[(8+h)*4+0], w0, v); v = fmaf(s_aiw[(8+h)*4+1], w1, v);
            v = fmaf(s_aiw[(8+h)*4+2], w2, v); v = fmaf(s_aiw[(8+h)*4+3], w3, v);
            qh[h] = q; kh[h] = k;
            __stcg(&g_kv[((b*4 + h) << 12) + off], make_float2(k, v));
        }
        __stcg(&g_q4[pbase + off], make_float4(qh[0], qh[1], qh[2], qh[3]));
        float red[16];
        #pragma unroll
        for (int h = 0; h < 4; h++) {
            red[h] = qh[h]; red[4+h] = qh[h]; red[8+h] = kh[h]; red[12+h] = kh[h];
        }
        #pragma unroll
        for (int o = 16; o > 0; o >>= 1) {
            #pragma unroll
            for (int h = 0; h < 4; h++) {
                red[h]    = fminf(red[h],    __shfl_xor_sync(0xFFFFFFFFu, red[h],    o));
                red[4+h]  = fmaxf(red[4+h],  __shfl_xor_sync(0xFFFFFFFFu, red[4+h],  o));
                red[8+h]  = fminf(red[8+h],  __shfl_xor_sync(0xFFFFFFFFu, red[8+h],  o));
                red[12+h] = fmaxf(red[12+h], __shfl_xor_sync(0xFFFFFFFFu, red[12+h], o));
            }
        }
        if ((tid & 31) == 0) {
            #pragma unroll
            for (int i = 0; i < 16; i++) s_red[tid >> 5][i] = red[i];
        }
    }
    __syncthreads();
    if (tid < 16) {
        const bool ismax = (tid >> 2) & 1;
        float v = s_red[0][tid];
        #pragma unroll
        for (int wq = 1; wq < 16; wq++)
            v = ismax ? fmaxf(v, s_red[wq][tid]) : fminf(v, s_red[wq][tid]);
        g_red[b][rank][tid] = v;
    }
    csync();

    if (tid < 16) {
        const bool ismax = (tid >> 2) & 1;
        float v = __ldcg(&g_red[b][0][tid]);
        #pragma unroll
        for (int r = 1; r < 8; r++) {
            const float u = __ldcg(&g_red[b][r][tid]);
            v = ismax ? fmaxf(v, u) : fminf(v, u);
        }
        s_meta[tid] = v;
    }
    {
        const int head = rank >> 1;
        float4*       dst = (float4*)s_buf;
        const float4* src = (const float4*)&g_kv[((b*4 + head) << 12)];
        dst[tid]        = __ldcg(&src[tid]);
        dst[tid + 1024] = __ldcg(&src[tid + 1024]);
        __syncthreads();

        const float amin = s_meta[head],     amax = s_meta[4 + head];
        const float kmn  = s_meta[8 + head], kmx  = s_meta[12 + head];
        const float hs   = fmaxf((amax - amin) * (1.0f/60.0f), 1e-30f);
        const int   lane = tid & 31;
        const int   n    = ((rank & 1) << 5) + (tid >> 5);
        const float a2   = (amin + (float)(n - 1) * hs) * LOG2E;
        const float m2   = fmaxf(a2 * kmn, a2 * kmx);

        float num = 0.f, den = 0.f;
        const float2* p2 = (const float2*)s_buf;
        #pragma unroll 8
        for (int jj = 0; jj < 128; jj++) {
            const float2 kv = p2[lane + (jj << 5)];
            const float  e  = fexp2(fmaf(a2, kv.x, -m2));
            num = fmaf(e, kv.y, num);
            den += e;
        }
        #pragma unroll
        for (int o = 16; o > 0; o >>= 1) {
            num += __shfl_xor_sync(0xFFFFFFFFu, num, o);
            den += __shfl_xor_sync(0xFFFFFFFFu, den, o);
        }
        if (lane == 0)
            __stcg(&g_tab[(b*4 + head)*64 + n], __fdividef(num, den));
    }
    csync();

    if (tid < 256) s_buf[tid] = __ldcg(&g_tab[b*256 + tid]);
    __syncthreads();
    if (low) {
        const float4 q4 = __ldcg(&g_q4[pbase + off]);
        const float qa[4] = { q4.x, q4.y, q4.z, q4.w };
        float oh[4];
        #pragma unroll
        for (int h = 0; h < 4; h++) {
            const float amin = s_meta[h];
            const float hs   = fmaxf((s_meta[4+h] - amin) * (1.0f/60.0f), 1e-30f);
            float sr = (qa[h] - amin) * __fdividef(1.0f, hs);
            sr = fminf(fmaxf(sr, 0.0f), 60.0f);
            const float fi = floorf(sr);
            const int   i0 = (int)fi;
            const float f  = sr - fi;
            const float* t = &s_buf[(h << 6) + i0];
            const float fm1 = f + 1.0f, f1 = f - 1.0f, f2 = f - 2.0f;
            const float c0 = -f  * f1 * f2 * (1.0f/6.0f);
            const float c1 =  fm1 * f1 * f2 * 0.5f;
            const float c2 = -fm1 * f  * f2 * 0.5f;
            const float c3 =  fm1 * f  * f1 * (1.0f/6.0f);
            oh[h] = c0*t[0] + c1*t[1] + c2*t[2] + c3*t[3];
        }
        __stcg(&g_o4[pbase + off], make_float4(oh[0], oh[1], oh[2], oh[3]));
    }
    csync();

    if (low) {
        float sx = 0.f, sy = 0.f, sz = 0.f, sw = 0.f, cnt = 0.f;
        #pragma unroll
        for (int dy = -1; dy <= 1; dy++) {
            const int yy = y + dy;
            if ((unsigned)yy >= 64u) continue;
            #pragma unroll
            for (int dx = -1; dx <= 1; dx++) {
                const int xc = xx + dx;
                if ((unsigned)xc >= 64u) continue;
                const float4 o = __ldcg(&g_o4[pbase + (yy << 6) + xc]);
                sx += o.x; sy += o.y; sz += o.z; sw += o.w;
                cnt += 1.0f;
            }
        }
        float oc[4];
        #pragma unroll
        for (int c = 0; c < 4; c++) {
            float pr = cnt * s_aob[c];
            pr = fmaf(s_aow[c*4+0], sx, pr); pr = fmaf(s_aow[c*4+1], sy, pr);
            pr = fmaf(s_aow[c*4+2], sz, pr); pr = fmaf(s_aow[c*4+3], sw, pr);
            oc[c] = pr * (1.0f/9.0f);
        }
        __stcg(&g_w34[pbase + off], make_float4(oc[0], oc[1], oc[2], oc[3]));
    }
    csync();

    if (low) {
        const float4 ctr = __ldcg(&g_w34[pbase + off]);
        float n0 = 0.f, n1 = 0.f, n2 = 0.f, n3 = 0.f;
        float sf[8];
        float4 xctr = make_float4(0.f, 0.f, 0.f, 0.f);
        #pragma unroll
        for (int o = 0; o < 8; o++) sf[o] = s_spb[o];
        #pragma unroll
        for (int dy = -1; dy <= 1; dy++) {
            const int yy = y + dy;
            if ((unsigned)yy >= 64u) continue;
            #pragma unroll
            for (int dx = -1; dx <= 1; dx++) {
                const int xc = xx + dx;
                if ((unsigned)xc >= 64u) continue;
                const int s2 = (yy << 6) + xc;
                if (!(dy == 0 && dx == 0)) {
                    const float4 v = __ldcg(&g_w34[pbase + s2]);
                    n0 += v.x; n1 += v.y; n2 += v.z; n3 += v.w;
                }
                const float4 xv = __ldcg(&g_x4[pbase + s2]);
                if (dy == 0 && dx == 0) xctr = xv;
                const int wtap = (dy + 1)*3 + (dx + 1);
                #pragma unroll
                for (int o = 0; o < 8; o++) {
                    float a = sf[o];
                    a = fmaf(s_spw[(o*4 + 0)*9 + wtap], xv.x, a);
                    a = fmaf(s_spw[(o*4 + 1)*9 + wtap], xv.y, a);
                    a = fmaf(s_spw[(o*4 + 2)*9 + wtap], xv.z, a);
                    a = fmaf(s_spw[(o*4 + 3)*9 + wtap], xv.w, a);
                    sf[o] = a;
                }
            }
        }
        float wet4[4];
        wet4[0] = fmaf(8.0f*ctr.x - n0, 0.04f, ctr.x);
        wet4[1] = fmaf(8.0f*ctr.y - n1, 0.04f, ctr.y);
        wet4[2] = fmaf(8.0f*ctr.z - n2, 0.04f, ctr.z);
        wet4[3] = fmaf(8.0f*ctr.w - n3, 0.04f, ctr.w);

        const float xc4[4] = { xctr.x, xctr.y, xctr.z, xctr.w };
        #pragma unroll
        for (int c = 0; c < 4; c++) {
            float pr = s_ob[c];
            #pragma unroll
            for (int jq = 0; jq < 8; jq++) pr = fmaf(s_ow[c*12 + jq],     sf[jq],   pr);
            #pragma unroll
            for (int jq = 0; jq < 4; jq++) pr = fmaf(s_ow[c*12 + 8 + jq], wet4[jq], pr);
            out[((b*4 + c) << 12) + off] = fmaf(xc4[c], 0.7f, 0.3f * pr);
        }
    }
}

// ---------------- launcher ---------------------------------------------------
extern "C" void kernel_launch(void* const* d_in, const int* in_sizes, int n_in,
                              void* d_out, int out_size)
{
    const float* x   = (const float*)d_in[0];
    const float* rw  = (const float*)d_in[1];
    const float* rd  = (const float*)d_in[2];
    const float* spw = (const float*)d_in[4];
    const float* spb = (const float*)d_in[5];
    const float* fw  = (const float*)d_in[6];
    const float* fb  = (const float*)d_in[7];
    const float* d1w = (const float*)d_in[8];
    const float* d1b = (const float*)d_in[9];
    const float* d2w = (const float*)d_in[10];
    const float* d2b = (const float*)d_in[11];
    const float* aiw = (const float*)d_in[12];
    const float* aib = (const float*)d_in[13];
    const float* aow = (const float*)d_in[14];
    const float* aob = (const float*)d_in[15];
    const float* ow  = (const float*)d_in[16];
    const float* ob  = (const float*)d_in[17];
    float* out = (float*)d_out;

    // Try the cluster-16 (nonportable) config; fall back to proven cluster-8.
    bool use16 = false;
    if (cudaFuncSetAttribute(fused16,
            cudaFuncAttributeNonPortableClusterSizeAllowed, 1) == cudaSuccess) {
        cudaLaunchConfig_t qcfg = {};
        qcfg.gridDim  = dim3(16, 4, 1);
        qcfg.blockDim = dim3(512, 1, 1);
        qcfg.dynamicSmemBytes = 0;
        qcfg.stream = 0;
        int maxC = 0;
        if (cudaOccupancyMaxPotentialClusterSize(&maxC, fused16, &qcfg)
                == cudaSuccess && maxC >= 16)
            use16 = true;
    }
    cudaGetLastError();  // clear any sticky error from queries

    if (use16) {
        cudaLaunchConfig_t cfg = {};
        cfg.gridDim  = dim3(16, 4, 1);
        cfg.blockDim = dim3(512, 1, 1);
        cfg.dynamicSmemBytes = 0;
        cfg.stream = 0;
        cudaLaunchAttribute attrs[1];
        attrs[0].id = cudaLaunchAttributeClusterDimension;
        attrs[0].val.clusterDim = {16, 1, 1};
        cfg.attrs = attrs;
        cfg.numAttrs = 1;
        if (cudaLaunchKernelEx(&cfg, fused16, x, rw, rd, fw, fb,
                               d1w, d1b, d2w, d2b, aiw, aib, aow, aob,
                               spw, spb, ow, ob, out) == cudaSuccess)
            return;
        cudaGetLastError();  // clear and fall through to fallback
    }

    fused8<<<dim3(8, 4), 1024>>>(x, rw, rd, fw, fb, d1w, d1b, d2w, d2b,
                                 aiw, aib, aow, aob, spw, spb, ow, ob, out);
}

// round 12
// speedup vs baseline: 1.0491x; 1.0491x over previous
#include <cuda_runtime.h>

// LatentReverb fused single-kernel v6 (= R8 baseline + pre-rotated padded sA)
// B=4, C=4, H=W=64, NREF=16; DECAY=0.8, WET_MIX=0.3, FEEDBACK=0.4, ROOM=0.5
// Primary:  grid (16,4), cluster 16 (nonportable), 512 thr/CTA, 4 rows/CTA.
// Fallback: grid (8,4),  cluster 8,               1024 thr/CTA, 8 rows/CTA.

#define LOG2E 1.4426950408889634f

// ---------------- scratch (static device globals; no allocation) -------------
__device__ float4 g_fb[2][4*4096];   // ping-pong feedback state (channel-last)
__device__ float4 g_x4  [4*4096];    // x transposed to channel-last
__device__ float4 g_q4  [4*4096];    // per-pixel q (4 heads)
__device__ float2 g_kv  [16*4096];   // per (b,h): (k, v)
__device__ float  g_red [4][16][16]; // per (b, cta): 16 partial min/max values
__device__ float  g_tab [1024];      // per (b,h): softmax-output table
__device__ float4 g_o4  [4*4096];    // (fallback only)
__device__ float4 g_w34 [4*4096];    // (fallback only)

// ---------------- helpers ----------------------------------------------------
__device__ __forceinline__ float fexp2(float x) {
    float y;
    asm("ex2.approx.ftz.f32 %0, %1;" : "=f"(y) : "f"(x));
    return y;
}
__device__ __forceinline__ float fsig(float x) {
    return __fdividef(1.0f, 1.0f + fexp2(-LOG2E * x));
}
__device__ __forceinline__ float fadef(int i) {
    float v = 1.0f;
    if (i < 4)   v = 0.6f + (0.4f/3.0f) * (float)i;
    if (i >= 60) v = 0.6f + (0.4f/3.0f) * (float)(63 - i);
    return v;
}
__device__ __forceinline__ void csync() {
    asm volatile("barrier.cluster.arrive.aligned;" ::: "memory");
    asm volatile("barrier.cluster.wait.aligned;"   ::: "memory");
}

// 16-FMA accumulation of one conv tap (float4 input, float4 weights over oc)
#define CONV_TAP(OFF, WT)                                                     \
    {                                                                         \
        const float4 v  = sAp[OFF];                                           \
        const float4 wa = fw4[(WT)*4 + 0], wb = fw4[(WT)*4 + 1];              \
        const float4 wc = fw4[(WT)*4 + 2], wd = fw4[(WT)*4 + 3];              \
        r0 = fmaf(wa.x, v.x, r0); r1 = fmaf(wa.y, v.x, r1);                   \
        r2 = fmaf(wa.z, v.x, r2); r3 = fmaf(wa.w, v.x, r3);                   \
        r0 = fmaf(wb.x, v.y, r0); r1 = fmaf(wb.y, v.y, r1);                   \
        r2 = fmaf(wb.z, v.y, r2); r3 = fmaf(wb.w, v.y, r3);                   \
        r0 = fmaf(wc.x, v.z, r0); r1 = fmaf(wc.y, v.z, r1);                   \
        r2 = fmaf(wc.z, v.z, r2); r3 = fmaf(wc.w, v.z, r3);                   \
        r0 = fmaf(wd.x, v.w, r0); r1 = fmaf(wd.y, v.w, r1);                   \
        r2 = fmaf(wd.z, v.w, r2); r3 = fmaf(wd.w, v.w, r3);                   \
    }

// =============================================================================
// PRIMARY kernel: cluster 16, 512 threads, 4 rows/CTA, TBL_N=32 span 28
// sA is stored PRE-ROTATED (x-roll applied at store) and PRE-PADDED (66-wide
// rows, cols 0/65 zero; row-OOB rows zeroed via fade) so the conv inner loop
// is pure immediate-offset LDS + FMA (no ALU, no branches).
// =============================================================================
__global__ void __launch_bounds__(512, 1) fused16(
    const float* __restrict__ x,
    const float* __restrict__ rw,  const float* __restrict__ rd,
    const float* __restrict__ fw,  const float* __restrict__ fbias,
    const float* __restrict__ d1w, const float* __restrict__ d1b,
    const float* __restrict__ d2w, const float* __restrict__ d2b,
    const float* __restrict__ aiw, const float* __restrict__ aib,
    const float* __restrict__ aow, const float* __restrict__ aob,
    const float* __restrict__ spw, const float* __restrict__ spb,
    const float* __restrict__ ow,  const float* __restrict__ ob,
    float* __restrict__ out)
{
    // unioned scratch:
    //  A: sA f4[0..395] (6 rows x 66), s_part f4[400..655]
    //  C: kv f4[0..2047]
    //  D/E: s_o f4[0..511], s_w34e f4[512..895]
    __shared__ __align__(16) float s_buf[8192];
    __shared__ __align__(16) float s_fw4[144];  // [tap][ic] float4 over oc
    __shared__ float s_cb[4];
    __shared__ float s_d1w[8], s_d1b[2], s_d2w[8], s_d2b[4];
    __shared__ float s_rw[16], s_rd[16], s_fade[64];
    __shared__ float s_aiw[48], s_aib[12], s_aow[16], s_aob[4];
    __shared__ float s_spw[288], s_spb[8], s_ow[48], s_ob[4];
    __shared__ float s_red[16][16];
    __shared__ float s_meta[16];
    __shared__ float s_tab[128];

    const int tid  = threadIdx.x;
    const int rank = blockIdx.x;               // cluster rank 0..15
    const int b    = blockIdx.y;

    if (tid < 144) {
        const int oc = tid & 3, ic = (tid >> 2) & 3, tap = tid >> 4;
        s_fw4[tid] = fw[(oc*4 + ic)*9 + tap];
    }
    if (tid < 4)   s_cb[tid]  = fbias[tid];
    if (tid < 8)   s_d1w[tid] = d1w[tid];
    if (tid < 2)   s_d1b[tid] = d1b[tid];
    if (tid < 8)   s_d2w[tid] = d2w[tid];
    if (tid < 4)   s_d2b[tid] = d2b[tid];
    if (tid < 16)  { s_rw[tid] = rw[tid]; s_rd[tid] = rd[tid]; }
    if (tid < 64)  s_fade[tid] = fadef(tid);
    if (tid < 48)  s_aiw[tid] = aiw[tid];
    if (tid < 12)  s_aib[tid] = aib[tid];
    if (tid < 16)  s_aow[tid] = aow[tid];
    if (tid < 4)   s_aob[tid] = aob[tid];
    {
        int i = tid; if (i < 288) s_spw[i] = spw[i];
        i = tid - 288; if (i >= 0 && i < 8)  s_spb[i] = spb[i];
        i = tid - 296; if (i >= 0 && i < 48) s_ow[i]  = ow[i];
        i = tid - 344; if (i >= 0 && i < 4)  s_ob[i]  = ob[i];
    }

    float4* sA     = (float4*)s_buf;           // 6 rows x 66 (padded)
    float4* s_part = (float4*)s_buf + 400;
    const float4* fw4 = (const float4*)s_fw4;

    // zero the pad columns (0 and 65) of each sA row — written once, staging
    // stores only touch cols 1..64.
    if (tid < 12) {
        const int r = tid >> 1, c = (tid & 1) * 65;
        sA[r*66 + c] = make_float4(0.f, 0.f, 0.f, 0.f);
    }

    const bool low  = tid < 256;
    const int  pix  = tid & 255;
    const int  y0   = rank << 2;
    const int  y    = y0 + (pix >> 6);
    const int  xx   = pix & 63;
    const int  off  = (y << 6) + xx;
    const int  pbase = b << 12;

    // ---- init: fb = 0.1*x; x to channel-last -----------------------------
    float fb0 = 0.f, fb1 = 0.f, fb2 = 0.f, fb3 = 0.f;
    float w0 = 0.f, w1 = 0.f, w2 = 0.f, w3 = 0.f;
    if (low) {
        const float x0 = x[((b*4 + 0) << 12) + off];
        const float x1 = x[((b*4 + 1) << 12) + off];
        const float x2 = x[((b*4 + 2) << 12) + off];
        const float x3 = x[((b*4 + 3) << 12) + off];
        __stcg(&g_x4[pbase + off], make_float4(x0, x1, x2, x3));
        fb0 = 0.1f*x0; fb1 = 0.1f*x1; fb2 = 0.1f*x2; fb3 = 0.1f*x3;
        __stcg(&g_fb[0][pbase + off], make_float4(fb0, fb1, fb2, fb3));
    }
    __syncthreads();
    csync();

    // ---- phase A: 16 reflections, one csync each -------------------------
    float decay = 1.0f;
    int ys2p = 0, xs2p = 0;
    for (int j = 0; j < 16; j++) {
        const float dly = s_rd[j] * 3.0f;      // exact small int
        const int ys = ((int)dly)          & 63;
        const int xs = ((int)(2.0f * dly)) & 63;

        const float4* Bp = g_fb[j & 1] + pbase;
        if (tid < 384) {
            const int r  = tid >> 6, px = tid & 63;
            const int gy = y0 - 1 + r;                   // conv row (may be OOB)
            const int srow = (gy - ys) & 63;
            float4 v = __ldcg(&Bp[(srow << 6) + px]);
            if (j >= 2) {
                const float t = 0.08f * s_fade[srow] * s_fade[px];
                const float4 v2 = __ldcg(
                    &Bp[(((srow - ys2p) & 63) << 6) + ((px - xs2p) & 63)]);
                v.x = fmaf(t, v2.x, v.x); v.y = fmaf(t, v2.y, v.y);
                v.z = fmaf(t, v2.z, v.z); v.w = fmaf(t, v2.w, v.w);
            }
            const int xc = (px + xs) & 63;               // conv x-position
            float fo = s_fade[gy & 63] * s_fade[xc];
            if ((unsigned)gy >= 64u) fo = 0.f;           // conv zero-pad row
            v.x *= fo; v.y *= fo; v.z *= fo; v.w *= fo;
            sA[r*66 + 1 + xc] = v;                       // pre-rotated store
        }
        float fA0 = fb0, fA1 = fb1, fA2 = fb2, fA3 = fb3;
        if (low && j >= 2) {
            const float t = 0.08f * s_fade[y] * s_fade[xx];
            const float4 v2 = __ldcg(
                &Bp[(((y - ys2p) & 63) << 6) + ((xx - xs2p) & 63)]);
            fA0 = fmaf(t, v2.x, fA0); fA1 = fmaf(t, v2.y, fA1);
            fA2 = fmaf(t, v2.z, fA2); fA3 = fmaf(t, v2.w, fA3);
        }
        __syncthreads();

        // tap-split conv3x3 — pure immediate-offset LDS + FMA
        const int rbase = pix >> 6;                      // local row 0..3
        const float4* sAp = sA + (rbase + 1)*66 + (xx + 1);
        float r0, r1, r2, r3;
        if (low) {
            r0 = s_cb[0]; r1 = s_cb[1]; r2 = s_cb[2]; r3 = s_cb[3];
            CONV_TAP(-67, 0)   // (-1,-1)
            CONV_TAP(-66, 1)   // (-1, 0)
            CONV_TAP(-65, 2)   // (-1,+1)
            CONV_TAP(-1,  3)   // ( 0,-1)
        } else {
            r0 = 0.f; r1 = 0.f; r2 = 0.f; r3 = 0.f;
            CONV_TAP(0,   4)   // ( 0, 0)
            CONV_TAP(1,   5)   // ( 0,+1)
            CONV_TAP(65,  6)   // (+1,-1)
            CONV_TAP(66,  7)   // (+1, 0)
            CONV_TAP(67,  8)   // (+1,+1)
            s_part[pix] = make_float4(r0, r1, r2, r3);
        }
        __syncthreads();

        if (low) {
            const float4 p4 = s_part[pix];
            r0 += p4.x; r1 += p4.y; r2 += p4.z; r3 += p4.w;

            float u0 = s_d1b[0], u1 = s_d1b[1];
            u0 = fmaf(s_d1w[0], r0, u0); u1 = fmaf(s_d1w[4], r0, u1);
            u0 = fmaf(s_d1w[1], r1, u0); u1 = fmaf(s_d1w[5], r1, u1);
            u0 = fmaf(s_d1w[2], r2, u0); u1 = fmaf(s_d1w[6], r2, u1);
            u0 = fmaf(s_d1w[3], r3, u0); u1 = fmaf(s_d1w[7], r3, u1);
            u0 = u0 * fsig(u0);
            u1 = u1 * fsig(u1);
            const float rd0 = r0 * fsig(s_d2b[0] + s_d2w[0]*u0 + s_d2w[1]*u1);
            const float rd1 = r1 * fsig(s_d2b[1] + s_d2w[2]*u0 + s_d2w[3]*u1);
            const float rd2 = r2 * fsig(s_d2b[2] + s_d2w[4]*u0 + s_d2w[5]*u1);
            const float rd3 = r3 * fsig(s_d2b[3] + s_d2w[6]*u0 + s_d2w[7]*u1);

            const float wscale = fsig(s_rw[j]) * decay * 3.0f;
            w0 = fmaf(rd0, wscale, w0); w1 = fmaf(rd1, wscale, w1);
            w2 = fmaf(rd2, wscale, w2); w3 = fmaf(rd3, wscale, w3);

            if (j < 15) {
                fb0 = fmaf(rd0, 0.24f, fA0); fb1 = fmaf(rd1, 0.24f, fA1);
                fb2 = fmaf(rd2, 0.24f, fA2); fb3 = fmaf(rd3, 0.24f, fA3);
                __stcg(&g_fb[(j + 1) & 1][pbase + off],
                       make_float4(fb0, fb1, fb2, fb3));
            }
        }
        ys2p = ((int)(dly * 0.5f)) & 63;
        xs2p = ((int)dly)          & 63;
        decay *= 0.8f;
        if (j < 15) csync();
    }

    // ---- phase B: qkv + min/max reduction --------------------------------
    if (low) {
        float qh[4], kh[4];
        #pragma unroll
        for (int h = 0; h < 4; h++) {
            float q = s_aib[h], k = s_aib[4 + h], v = s_aib[8 + h];
            q = fmaf(s_aiw[h*4+0],     w0, q); q = fmaf(s_aiw[h*4+1],     w1, q);
            q = fmaf(s_aiw[h*4+2],     w2, q); q = fmaf(s_aiw[h*4+3],     w3, q);
            k = fmaf(s_aiw[(4+h)*4+0], w0, k); k = fmaf(s_aiw[(4+h)*4+1], w1, k);
            k = fmaf(s_aiw[(4+h)*4+2], w2, k); k = fmaf(s_aiw[(4+h)*4+3], w3, k);
            v = fmaf(s_aiw[(8+h)*4+0], w0, v); v = fmaf(s_aiw[(8+h)*4+1], w1, v);
            v = fmaf(s_aiw[(8+h)*4+2], w2, v); v = fmaf(s_aiw[(8+h)*4+3], w3, v);
            qh[h] = q; kh[h] = k;
            __stcg(&g_kv[((b*4 + h) << 12) + off], make_float2(k, v));
        }
        __stcg(&g_q4[pbase + off], make_float4(qh[0], qh[1], qh[2], qh[3]));
        float red[16];
        #pragma unroll
        for (int h = 0; h < 4; h++) {
            red[h] = qh[h]; red[4+h] = qh[h]; red[8+h] = kh[h]; red[12+h] = kh[h];
        }
        #pragma unroll
        for (int o = 16; o > 0; o >>= 1) {
            #pragma unroll
            for (int h = 0; h < 4; h++) {
                red[h]    = fminf(red[h],    __shfl_xor_sync(0xFFFFFFFFu, red[h],    o));
                red[4+h]  = fmaxf(red[4+h],  __shfl_xor_sync(0xFFFFFFFFu, red[4+h],  o));
                red[8+h]  = fminf(red[8+h],  __shfl_xor_sync(0xFFFFFFFFu, red[8+h],  o));
                red[12+h] = fmaxf(red[12+h], __shfl_xor_sync(0xFFFFFFFFu, red[12+h], o));
            }
        }
        if ((tid & 31) == 0) {
            #pragma unroll
            for (int i = 0; i < 16; i++) s_red[tid >> 5][i] = red[i];
        }
    }
    __syncthreads();
    if (tid < 16) {
        const bool ismax = (tid >> 2) & 1;
        float v = s_red[0][tid];
        #pragma unroll
        for (int wq = 1; wq < 8; wq++)
            v = ismax ? fmaxf(v, s_red[wq][tid]) : fminf(v, s_red[wq][tid]);
        g_red[b][rank][tid] = v;
    }
    csync();

    // ---- phase C: softmax table, 32 nodes/head, 8 nodes/CTA --------------
    if (tid < 16) {
        const bool ismax = (tid >> 2) & 1;
        float v = __ldcg(&g_red[b][0][tid]);
        #pragma unroll
        for (int r = 1; r < 16; r++) {
            const float u = __ldcg(&g_red[b][r][tid]);
            v = ismax ? fmaxf(v, u) : fminf(v, u);
        }
        s_meta[tid] = v;
    }
    {
        const int head = rank >> 2;
        float4*       dst = (float4*)s_buf;
        const float4* src = (const float4*)&g_kv[((b*4 + head) << 12)];
        #pragma unroll
        for (int k4 = 0; k4 < 4; k4++)
            dst[tid + (k4 << 9)] = __ldcg(&src[tid + (k4 << 9)]);
        __syncthreads();

        const float amin = s_meta[head],     amax = s_meta[4 + head];
        const float kmn  = s_meta[8 + head], kmx  = s_meta[12 + head];
        const float hs   = fmaxf((amax - amin) * (1.0f/28.0f), 1e-30f);
        const int   nloc = tid >> 6;                 // 0..7
        const int   l64  = tid & 63;
        const int   n    = ((rank & 3) << 3) + nloc; // 0..31
        const float a2   = (amin + (float)(n - 1) * hs) * LOG2E;
        const float m2   = fmaxf(a2 * kmn, a2 * kmx);

        float num = 0.f, den = 0.f;
        const float2* p2 = (const float2*)s_buf;
        #pragma unroll 8
        for (int jj = 0; jj < 64; jj++) {
            const float2 kv = p2[l64 + (jj << 6)];
            const float  e  = fexp2(fmaf(a2, kv.x, -m2));
            num = fmaf(e, kv.y, num);
            den += e;
        }
        #pragma unroll
        for (int o = 16; o > 0; o >>= 1) {
            num += __shfl_xor_sync(0xFFFFFFFFu, num, o);
            den += __shfl_xor_sync(0xFFFFFFFFu, den, o);
        }
        if ((tid & 31) == 0) {
            s_red[tid >> 5][0] = num;
            s_red[tid >> 5][1] = den;
        }
        __syncthreads();
        if (tid < 8) {
            const float nm = s_red[2*tid][0] + s_red[2*tid + 1][0];
            const float dn = s_red[2*tid][1] + s_red[2*tid + 1][1];
            __stcg(&g_tab[(b*4 + head)*32 + ((rank & 3) << 3) + tid],
                   __fdividef(nm, dn));
        }
    }
    csync();

    // ---- phase D: interp o for 8 rows (own 4 + 2-row halos) into SMEM ----
    if (tid < 128) s_tab[tid] = __ldcg(&g_tab[b*128 + tid]);
    __syncthreads();
    float4* s_o = (float4*)s_buf;              // [8][64]
    {
        const int erow = tid >> 6, col = tid & 63;
        const int ry   = y0 - 2 + erow;
        float4 ov = make_float4(0.f, 0.f, 0.f, 0.f);
        if ((unsigned)ry < 64u) {
            const float4 q4 = __ldcg(&g_q4[pbase + (ry << 6) + col]);
            const float qa[4] = { q4.x, q4.y, q4.z, q4.w };
            float oh[4];
            #pragma unroll
            for (int h = 0; h < 4; h++) {
                const float amin = s_meta[h];
                const float hs = fmaxf((s_meta[4+h] - amin)*(1.0f/28.0f), 1e-30f);
                float sr = (qa[h] - amin) * __fdividef(1.0f, hs);
                sr = fminf(fmaxf(sr, 0.0f), 28.0f);
                const float fi = floorf(sr);
                const int   i0 = (int)fi;
                const float f  = sr - fi;
                const float* t = &s_tab[(h << 5) + i0];
                const float fm1 = f + 1.0f, f1 = f - 1.0f, f2 = f - 2.0f;
                const float c0 = -f  * f1 * f2 * (1.0f/6.0f);
                const float c1 =  fm1 * f1 * f2 * 0.5f;
                const float c2 = -fm1 * f  * f2 * 0.5f;
                const float c3 =  fm1 * f  * f1 * (1.0f/6.0f);
                oh[h] = c0*t[0] + c1*t[1] + c2*t[2] + c3*t[3];
            }
            ov = make_float4(oh[0], oh[1], oh[2], oh[3]);
        }
        s_o[tid] = ov;
    }
    __syncthreads();

    // ---- phase E1: box blur + attn out-projection for 6 rows into SMEM ---
    float4* s_w34e = (float4*)s_buf + 512;     // [6][64]
    if (tid < 384) {
        const int brow = tid >> 6, col = tid & 63;
        const int row  = y0 - 1 + brow;
        if ((unsigned)row < 64u) {
            float sx = 0.f, sy = 0.f, sz = 0.f, sw = 0.f, cnt = 0.f;
            #pragma unroll
            for (int dy = -1; dy <= 1; dy++) {
                const int r2 = row + dy;
                if ((unsigned)r2 >= 64u) continue;
                const int er = brow + 1 + dy;
                #pragma unroll
                for (int dx = -1; dx <= 1; dx++) {
                    const int c2 = col + dx;
                    if ((unsigned)c2 >= 64u) continue;
                    const float4 o = s_o[(er << 6) + c2];
                    sx += o.x; sy += o.y; sz += o.z; sw += o.w;
                    cnt += 1.0f;
                }
            }
            float oc[4];
            #pragma unroll
            for (int c = 0; c < 4; c++) {
                float pr = cnt * s_aob[c];
                pr = fmaf(s_aow[c*4+0], sx, pr); pr = fmaf(s_aow[c*4+1], sy, pr);
                pr = fmaf(s_aow[c*4+2], sz, pr); pr = fmaf(s_aow[c*4+3], sw, pr);
                oc[c] = pr * (1.0f/9.0f);
            }
            s_w34e[tid] = make_float4(oc[0], oc[1], oc[2], oc[3]);
        }
    }
    __syncthreads();

    // ---- phase E2: edge enhance + spatial conv + 1x1 out + mix -----------
    if (low) {
        const int lrow = pix >> 6;
        const float4 ctr = s_w34e[((lrow + 1) << 6) + xx];
        float n0 = 0.f, n1 = 0.f, n2 = 0.f, n3 = 0.f;
        float sf[8];
        float4 xctr = make_float4(0.f, 0.f, 0.f, 0.f);
        #pragma unroll
        for (int o = 0; o < 8; o++) sf[o] = s_spb[o];
        #pragma unroll
        for (int dy = -1; dy <= 1; dy++) {
            const int yy = y + dy;
            if ((unsigned)yy >= 64u) continue;
            const int wr = lrow + 1 + dy;
            #pragma unroll
            for (int dx = -1; dx <= 1; dx++) {
                const int xc = xx + dx;
                if ((unsigned)xc >= 64u) continue;
                if (!(dy == 0 && dx == 0)) {
                    const float4 v = s_w34e[(wr << 6) + xc];
                    n0 += v.x; n1 += v.y; n2 += v.z; n3 += v.w;
                }
                const float4 xv = __ldcg(&g_x4[pbase + (yy << 6) + xc]);
                if (dy == 0 && dx == 0) xctr = xv;
                const int wtap = (dy + 1)*3 + (dx + 1);
                #pragma unroll
                for (int o = 0; o < 8; o++) {
                    float a = sf[o];
                    a = fmaf(s_spw[(o*4 + 0)*9 + wtap], xv.x, a);
                    a = fmaf(s_spw[(o*4 + 1)*9 + wtap], xv.y, a);
                    a = fmaf(s_spw[(o*4 + 2)*9 + wtap], xv.z, a);
                    a = fmaf(s_spw[(o*4 + 3)*9 + wtap], xv.w, a);
                    sf[o] = a;
                }
            }
        }
        float wet4[4];
        wet4[0] = fmaf(8.0f*ctr.x - n0, 0.04f, ctr.x);
        wet4[1] = fmaf(8.0f*ctr.y - n1, 0.04f, ctr.y);
        wet4[2] = fmaf(8.0f*ctr.z - n2, 0.04f, ctr.z);
        wet4[3] = fmaf(8.0f*ctr.w - n3, 0.04f, ctr.w);

        const float xc4[4] = { xctr.x, xctr.y, xctr.z, xctr.w };
        #pragma unroll
        for (int c = 0; c < 4; c++) {
            float pr = s_ob[c];
            #pragma unroll
            for (int jq = 0; jq < 8; jq++) pr = fmaf(s_ow[c*12 + jq],     sf[jq],   pr);
            #pragma unroll
            for (int jq = 0; jq < 4; jq++) pr = fmaf(s_ow[c*12 + 8 + jq], wet4[jq], pr);
            out[((b*4 + c) << 12) + off] = fmaf(xc4[c], 0.7f, 0.3f * pr);
        }
    }
}

// =============================================================================
// FALLBACK kernel: proven config (cluster 8, 1024 thr, TBL 64 span 60)
// =============================================================================
__global__ void __cluster_dims__(8,1,1) __launch_bounds__(1024, 1) fused8(
    const float* __restrict__ x,
    const float* __restrict__ rw,  const float* __restrict__ rd,
    const float* __restrict__ fw,  const float* __restrict__ fbias,
    const float* __restrict__ d1w, const float* __restrict__ d1b,
    const float* __restrict__ d2w, const float* __restrict__ d2b,
    const float* __restrict__ aiw, const float* __restrict__ aib,
    const float* __restrict__ aow, const float* __restrict__ aob,
    const float* __restrict__ spw, const float* __restrict__ spb,
    const float* __restrict__ ow,  const float* __restrict__ ob,
    float* __restrict__ out)
{
    __shared__ __align__(16) float s_buf[8192];
    __shared__ __align__(16) float s_fw4[144];
    __shared__ float s_cb[4];
    __shared__ float s_d1w[8], s_d1b[2], s_d2w[8], s_d2b[4];
    __shared__ float s_rw[16], s_rd[16], s_fade[64];
    __shared__ float s_aiw[48], s_aib[12], s_aow[16], s_aob[4];
    __shared__ float s_spw[288], s_spb[8], s_ow[48], s_ob[4];
    __shared__ float s_red[16][16];
    __shared__ float s_meta[16];

    const int tid  = threadIdx.x;
    const int rank = blockIdx.x;
    const int b    = blockIdx.y;

    if (tid < 144) {
        const int oc = tid & 3, ic = (tid >> 2) & 3, tap = tid >> 4;
        s_fw4[tid] = fw[(oc*4 + ic)*9 + tap];
    }
    if (tid < 4)   s_cb[tid]  = fbias[tid];
    if (tid < 8)   s_d1w[tid] = d1w[tid];
    if (tid < 2)   s_d1b[tid] = d1b[tid];
    if (tid < 8)   s_d2w[tid] = d2w[tid];
    if (tid < 4)   s_d2b[tid] = d2b[tid];
    if (tid < 16)  { s_rw[tid] = rw[tid]; s_rd[tid] = rd[tid]; }
    if (tid < 64)  s_fade[tid] = fadef(tid);
    if (tid < 48)  s_aiw[tid] = aiw[tid];
    if (tid < 12)  s_aib[tid] = aib[tid];
    if (tid < 16)  s_aow[tid] = aow[tid];
    if (tid < 4)   s_aob[tid] = aob[tid];
    {
        int i = tid; if (i < 288) s_spw[i] = spw[i];
        i = tid - 288; if (i >= 0 && i < 8)  s_spb[i] = spb[i];
        i = tid - 296; if (i >= 0 && i < 48) s_ow[i]  = ow[i];
        i = tid - 344; if (i >= 0 && i < 4)  s_ob[i]  = ob[i];
    }

    const bool low  = tid < 512;
    const int  pix  = tid & 511;
    const int  y0   = rank << 3;
    const int  y    = y0 + (pix >> 6);
    const int  xx   = pix & 63;
    const int  off  = (y << 6) + xx;
    const int  pbase = b << 12;

    float fb0 = 0.f, fb1 = 0.f, fb2 = 0.f, fb3 = 0.f;
    float w0 = 0.f, w1 = 0.f, w2 = 0.f, w3 = 0.f;
    if (low) {
        const float x0 = x[((b*4 + 0) << 12) + off];
        const float x1 = x[((b*4 + 1) << 12) + off];
        const float x2 = x[((b*4 + 2) << 12) + off];
        const float x3 = x[((b*4 + 3) << 12) + off];
        __stcg(&g_x4[pbase + off], make_float4(x0, x1, x2, x3));
        fb0 = 0.1f*x0; fb1 = 0.1f*x1; fb2 = 0.1f*x2; fb3 = 0.1f*x3;
        __stcg(&g_fb[0][pbase + off], make_float4(fb0, fb1, fb2, fb3));
    }
    __syncthreads();
    csync();

    float4* sA     = (float4*)s_buf;
    float4* s_part = (float4*)s_buf + 768;
    const float4* fw4 = (const float4*)s_fw4;
    float decay = 1.0f;
    int ys2p = 0, xs2p = 0;
    for (int j = 0; j < 16; j++) {
        const float dly = s_rd[j] * 3.0f;
        const int ys = ((int)dly)          & 63;
        const int xs = ((int)(2.0f * dly)) & 63;

        const float4* Bp = g_fb[j & 1] + pbase;
        if (tid < 640) {
            const int r = tid >> 6, px = tid & 63;
            const int srow = (y0 - 1 + r - ys) & 63;
            float4 v = __ldcg(&Bp[(srow << 6) + px]);
            if (j >= 2) {
                const float t = 0.08f * s_fade[srow] * s_fade[px];
                const float4 v2 = __ldcg(
                    &Bp[(((srow - ys2p) & 63) << 6) + ((px - xs2p) & 63)]);
                v.x = fmaf(t, v2.x, v.x); v.y = fmaf(t, v2.y, v.y);
                v.z = fmaf(t, v2.z, v.z); v.w = fmaf(t, v2.w, v.w);
            }
            const float fo = s_fade[(y0 - 1 + r) & 63] * s_fade[(px + xs) & 63];
            v.x *= fo; v.y *= fo; v.z *= fo; v.w *= fo;
            sA[tid] = v;
        }
        float fA0 = fb0, fA1 = fb1, fA2 = fb2, fA3 = fb3;
        if (low && j >= 2) {
            const float t = 0.08f * s_fade[y] * s_fade[xx];
            const float4 v2 = __ldcg(
                &Bp[(((y - ys2p) & 63) << 6) + ((xx - xs2p) & 63)]);
            fA0 = fmaf(t, v2.x, fA0); fA1 = fmaf(t, v2.y, fA1);
            fA2 = fmaf(t, v2.z, fA2); fA3 = fmaf(t, v2.w, fA3);
        }
        __syncthreads();

        float r0, r1, r2, r3;
        if (low) { r0 = s_cb[0]; r1 = s_cb[1]; r2 = s_cb[2]; r3 = s_cb[3]; }
        else     { r0 = 0.f; r1 = 0.f; r2 = 0.f; r3 = 0.f; }
        const int rbase = pix >> 6;
        #pragma unroll
        for (int t5 = 0; t5 < 5; t5++) {
            int dy, dx;
            if (low) {
                if (t5 == 4) break;
                dy = (t5 < 3) ? -1 : 0;
                dx = (t5 < 3) ? (t5 - 1) : -1;
            } else {
                dy = (t5 < 2) ? 0 : 1;
                dx = (t5 < 2) ? t5 : (t5 - 3);
            }
            const int yy = y + dy, xc = xx + dx;
            if ((unsigned)yy >= 64u || (unsigned)xc >= 64u) continue;
            const float4 v = sA[((rbase + dy + 1) << 6) + ((xc - xs) & 63)];
            const int wt = ((dy + 1)*3 + (dx + 1)) << 2;
            const float4 wa = fw4[wt + 0], wb = fw4[wt + 1];
            const float4 wc = fw4[wt + 2], wd = fw4[wt + 3];
            r0 = fmaf(wa.x, v.x, r0); r1 = fmaf(wa.y, v.x, r1);
            r2 = fmaf(wa.z, v.x, r2); r3 = fmaf(wa.w, v.x, r3);
            r0 = fmaf(wb.x, v.y, r0); r1 = fmaf(wb.y, v.y, r1);
            r2 = fmaf(wb.z, v.y, r2); r3 = fmaf(wb.w, v.y, r3);
            r0 = fmaf(wc.x, v.z, r0); r1 = fmaf(wc.y, v.z, r1);
            r2 = fmaf(wc.z, v.z, r2); r3 = fmaf(wc.w, v.z, r3);
            r0 = fmaf(wd.x, v.w, r0); r1 = fmaf(wd.y, v.w, r1);
            r2 = fmaf(wd.z, v.w, r2); r3 = fmaf(wd.w, v.w, r3);
        }
        if (!low) s_part[pix] = make_float4(r0, r1, r2, r3);
        __syncthreads();

        if (low) {
            const float4 p4 = s_part[pix];
            r0 += p4.x; r1 += p4.y; r2 += p4.z; r3 += p4.w;

            float u0 = s_d1b[0], u1 = s_d1b[1];
            u0 = fmaf(s_d1w[0], r0, u0); u1 = fmaf(s_d1w[4], r0, u1);
            u0 = fmaf(s_d1w[1], r1, u0); u1 = fmaf(s_d1w[5], r1, u1);
            u0 = fmaf(s_d1w[2], r2, u0); u1 = fmaf(s_d1w[6], r2, u1);
            u0 = fmaf(s_d1w[3], r3, u0); u1 = fmaf(s_d1w[7], r3, u1);
            u0 = u0 * fsig(u0);
            u1 = u1 * fsig(u1);
            const float rd0 = r0 * fsig(s_d2b[0] + s_d2w[0]*u0 + s_d2w[1]*u1);
            const float rd1 = r1 * fsig(s_d2b[1] + s_d2w[2]*u0 + s_d2w[3]*u1);
            const float rd2 = r2 * fsig(s_d2b[2] + s_d2w[4]*u0 + s_d2w[5]*u1);
            const float rd3 = r3 * fsig(s_d2b[3] + s_d2w[6]*u0 + s_d2w[7]*u1);

            const float wscale = fsig(s_rw[j]) * decay * 3.0f;
            w0 = fmaf(rd0, wscale, w0); w1 = fmaf(rd1, wscale, w1);
            w2 = fmaf(rd2, wscale, w2); w3 = fmaf(rd3, wscale, w3);

            if (j < 15) {
                fb0 = fmaf(rd0, 0.24f, fA0); fb1 = fmaf(rd1, 0.24f, fA1);
                fb2 = fmaf(rd2, 0.24f, fA2); fb3 = fmaf(rd3, 0.24f, fA3);
                __stcg(&g_fb[(j + 1) & 1][pbase + off],
                       make_float4(fb0, fb1, fb2, fb3));
            }
        }
        ys2p = ((int)(dly * 0.5f)) & 63;
        xs2p = ((int)dly)          & 63;
        decay *= 0.8f;
        if (j < 15) csync();
    }

    if (low) {
        float qh[4], kh[4];
        #pragma unroll
        for (int h = 0; h < 4; h++) {
            float q = s_aib[h], k = s_aib[4 + h], v = s_aib[8 + h];
            q = fmaf(s_aiw[h*4+0],     w0, q); q = fmaf(s_aiw[h*4+1],     w1, q);
            q = fmaf(s_aiw[h*4+2],     w2, q); q = fmaf(s_aiw[h*4+3],     w3, q);
            k = fmaf(s_aiw[(4+h)*4+0], w0, k); k = fmaf(s_aiw[(4+h)*4+1], w1, k);
            k = fmaf(s_aiw[(4+h)*4+2], w2, k); k = fmaf(s_aiw[(4+h)*4+3], w3, k);
            v = fmaf(s_aiw[(8+h)*4+0], w0, v); v = fmaf(s_aiw[(8+h)*4+1], w1, v);
            v = fmaf(s_aiw[(8+h)*4+2], w2, v); v = fmaf(s_aiw[(8+h)*4+3], w3, v);
            qh[h] = q; kh[h] = k;
            __stcg(&g_kv[((b*4 + h) << 12) + off], make_float2(k, v));
        }
        __stcg(&g_q4[pbase + off], make_float4(qh[0], qh[1], qh[2], qh[3]));
        float red[16];
        #pragma unroll
        for (int h = 0; h < 4; h++) {
            red[h] = qh[h]; red[4+h] = qh[h]; red[8+h] = kh[h]; red[12+h] = kh[h];
        }
        #pragma unroll
        for (int o = 16; o > 0; o >>= 1) {
            #pragma unroll
            for (int h = 0; h < 4; h++) {
                red[h]    = fminf(red[h],    __shfl_xor_sync(0xFFFFFFFFu, red[h],    o));
                red[4+h]  = fmaxf(red[4+h],  __shfl_xor_sync(0xFFFFFFFFu, red[4+h],  o));
                red[8+h]  = fminf(red[8+h],  __shfl_xor_sync(0xFFFFFFFFu, red[8+h],  o));
                red[12+h] = fmaxf(red[12+h], __shfl_xor_sync(0xFFFFFFFFu, red[12+h], o));
            }
        }
        if ((tid & 31) == 0) {
            #pragma unroll
            for (int i = 0; i < 16; i++) s_red[tid >> 5][i] = red[i];
        }
    }
    __syncthreads();
    if (tid < 16) {
        const bool ismax = (tid >> 2) & 1;
        float v = s_red[0][tid];
        #pragma unroll
        for (int wq = 1; wq < 16; wq++)
            v = ismax ? fmaxf(v, s_red[wq][tid]) : fminf(v, s_red[wq][tid]);
        g_red[b][rank][tid] = v;
    }
    csync();

    if (tid < 16) {
        const bool ismax = (tid >> 2) & 1;
        float v = __ldcg(&g_red[b][0][tid]);
        #pragma unroll
        for (int r = 1; r < 8; r++) {
            const float u = __ldcg(&g_red[b][r][tid]);
            v = ismax ? fmaxf(v, u) : fminf(v, u);
        }
        s_meta[tid] = v;
    }
    {
        const int head = rank >> 1;
        float4*       dst = (float4*)s_buf;
        const float4* src = (const float4*)&g_kv[((b*4 + head) << 12)];
        dst[tid]        = __ldcg(&src[tid]);
        dst[tid + 1024] = __ldcg(&src[tid + 1024]);
        __syncthreads();

        const float amin = s_meta[head],     amax = s_meta[4 + head];
        const float kmn  = s_meta[8 + head], kmx  = s_meta[12 + head];
        const float hs   = fmaxf((amax - amin) * (1.0f/60.0f), 1e-30f);
        const int   lane = tid & 31;
        const int   n    = ((rank & 1) << 5) + (tid >> 5);
        const float a2   = (amin + (float)(n - 1) * hs) * LOG2E;
        const float m2   = fmaxf(a2 * kmn, a2 * kmx);

        float num = 0.f, den = 0.f;
        const float2* p2 = (const float2*)s_buf;
        #pragma unroll 8
        for (int jj = 0; jj < 128; jj++) {
            const float2 kv = p2[lane + (jj << 5)];
            const float  e  = fexp2(fmaf(a2, kv.x, -m2));
            num = fmaf(e, kv.y, num);
            den += e;
        }
        #pragma unroll
        for (int o = 16; o > 0; o >>= 1) {
            num += __shfl_xor_sync(0xFFFFFFFFu, num, o);
            den += __shfl_xor_sync(0xFFFFFFFFu, den, o);
        }
        if (lane == 0)
            __stcg(&g_tab[(b*4 + head)*64 + n], __fdividef(num, den));
    }
    csync();

    if (tid < 256) s_buf[tid] = __ldcg(&g_tab[b*256 + tid]);
    __syncthreads();
    if (low) {
        const float4 q4 = __ldcg(&g_q4[pbase + off]);
        const float qa[4] = { q4.x, q4.y, q4.z, q4.w };
        float oh[4];
        #pragma unroll
        for (int h = 0; h < 4; h++) {
            const float amin = s_meta[h];
            const float hs   = fmaxf((s_meta[4+h] - amin) * (1.0f/60.0f), 1e-30f);
            float sr = (qa[h] - amin) * __fdividef(1.0f, hs);
            sr = fminf(fmaxf(sr, 0.0f), 60.0f);
            const float fi = floorf(sr);
            const int   i0 = (int)fi;
            const float f  = sr - fi;
            const float* t = &s_buf[(h << 6) + i0];
            const float fm1 = f + 1.0f, f1 = f - 1.0f, f2 = f - 2.0f;
            const float c0 = -f  * f1 * f2 * (1.0f/6.0f);
            const float c1 =  fm1 * f1 * f2 * 0.5f;
            const float c2 = -fm1 * f  * f2 * 0.5f;
            const float c3 =  fm1 * f  * f1 * (1.0f/6.0f);
            oh[h] = c0*t[0] + c1*t[1] + c2*t[2] + c3*t[3];
        }
        __stcg(&g_o4[pbase + off], make_float4(oh[0], oh[1], oh[2], oh[3]));
    }
    csync();

    if (low) {
        float sx = 0.f, sy = 0.f, sz = 0.f, sw = 0.f, cnt = 0.f;
        #pragma unroll
        for (int dy = -1; dy <= 1; dy++) {
            const int yy = y + dy;
            if ((unsigned)yy >= 64u) continue;
            #pragma unroll
            for (int dx = -1; dx <= 1; dx++) {
                const int xc = xx + dx;
                if ((unsigned)xc >= 64u) continue;
                const float4 o = __ldcg(&g_o4[pbase + (yy << 6) + xc]);
                sx += o.x; sy += o.y; sz += o.z; sw += o.w;
                cnt += 1.0f;
            }
        }
        float oc[4];
        #pragma unroll
        for (int c = 0; c < 4; c++) {
            float pr = cnt * s_aob[c];
            pr = fmaf(s_aow[c*4+0], sx, pr); pr = fmaf(s_aow[c*4+1], sy, pr);
            pr = fmaf(s_aow[c*4+2], sz, pr); pr = fmaf(s_aow[c*4+3], sw, pr);
            oc[c] = pr * (1.0f/9.0f);
        }
        __stcg(&g_w34[pbase + off], make_float4(oc[0], oc[1], oc[2], oc[3]));
    }
    csync();

    if (low) {
        const float4 ctr = __ldcg(&g_w34[pbase + off]);
        float n0 = 0.f, n1 = 0.f, n2 = 0.f, n3 = 0.f;
        float sf[8];
        float4 xctr = make_float4(0.f, 0.f, 0.f, 0.f);
        #pragma unroll
        for (int o = 0; o < 8; o++) sf[o] = s_spb[o];
        #pragma unroll
        for (int dy = -1; dy <= 1; dy++) {
            const int yy = y + dy;
            if ((unsigned)yy >= 64u) continue;
            #pragma unroll
            for (int dx = -1; dx <= 1; dx++) {
                const int xc = xx + dx;
                if ((unsigned)xc >= 64u) continue;
                const int s2 = (yy << 6) + xc;
                if (!(dy == 0 && dx == 0)) {
                    const float4 v = __ldcg(&g_w34[pbase + s2]);
                    n0 += v.x; n1 += v.y; n2 += v.z; n3 += v.w;
                }
                const float4 xv = __ldcg(&g_x4[pbase + s2]);
                if (dy == 0 && dx == 0) xctr = xv;
                const int wtap = (dy + 1)*3 + (dx + 1);
                #pragma unroll
                for (int o = 0; o < 8; o++) {
                    float a = sf[o];
                    a = fmaf(s_spw[(o*4 + 0)*9 + wtap], xv.x, a);
                    a = fmaf(s_spw[(o*4 + 1)*9 + wtap], xv.y, a);
                    a = fmaf(s_spw[(o*4 + 2)*9 + wtap], xv.z, a);
                    a = fmaf(s_spw[(o*4 + 3)*9 + wtap], xv.w, a);
                    sf[o] = a;
                }
            }
        }
        float wet4[4];
        wet4[0] = fmaf(8.0f*ctr.x - n0, 0.04f, ctr.x);
        wet4[1] = fmaf(8.0f*ctr.y - n1, 0.04f, ctr.y);
        wet4[2] = fmaf(8.0f*ctr.z - n2, 0.04f, ctr.z);
        wet4[3] = fmaf(8.0f*ctr.w - n3, 0.04f, ctr.w);

        const float xc4[4] = { xctr.x, xctr.y, xctr.z, xctr.w };
        #pragma unroll
        for (int c = 0; c < 4; c++) {
            float pr = s_ob[c];
            #pragma unroll
            for (int jq = 0; jq < 8; jq++) pr = fmaf(s_ow[c*12 + jq],     sf[jq],   pr);
            #pragma unroll
            for (int jq = 0; jq < 4; jq++) pr = fmaf(s_ow[c*12 + 8 + jq], wet4[jq], pr);
            out[((b*4 + c) << 12) + off] = fmaf(xc4[c], 0.7f, 0.3f * pr);
        }
    }
}

// ---------------- launcher ---------------------------------------------------
extern "C" void kernel_launch(void* const* d_in, const int* in_sizes, int n_in,
                              void* d_out, int out_size)
{
    const float* x   = (const float*)d_in[0];
    const float* rw  = (const float*)d_in[1];
    const float* rd  = (const float*)d_in[2];
    const float* spw = (const float*)d_in[4];
    const float* spb = (const float*)d_in[5];
    const float* fw  = (const float*)d_in[6];
    const float* fb  = (const float*)d_in[7];
    const float* d1w = (const float*)d_in[8];
    const float* d1b = (const float*)d_in[9];
    const float* d2w = (const float*)d_in[10];
    const float* d2b = (const float*)d_in[11];
    const float* aiw = (const float*)d_in[12];
    const float* aib = (const float*)d_in[13];
    const float* aow = (const float*)d_in[14];
    const float* aob = (const float*)d_in[15];
    const float* ow  = (const float*)d_in[16];
    const float* ob  = (const float*)d_in[17];
    float* out = (float*)d_out;

    // Try the cluster-16 (nonportable) config; fall back to proven cluster-8.
    bool use16 = false;
    if (cudaFuncSetAttribute(fused16,
            cudaFuncAttributeNonPortableClusterSizeAllowed, 1) == cudaSuccess) {
        cudaLaunchConfig_t qcfg = {};
        qcfg.gridDim  = dim3(16, 4, 1);
        qcfg.blockDim = dim3(512, 1, 1);
        qcfg.dynamicSmemBytes = 0;
        qcfg.stream = 0;
        int maxC = 0;
        if (cudaOccupancyMaxPotentialClusterSize(&maxC, fused16, &qcfg)
                == cudaSuccess && maxC >= 16)
            use16 = true;
    }
    cudaGetLastError();  // clear any sticky error from queries

    if (use16) {
        cudaLaunchConfig_t cfg = {};
        cfg.gridDim  = dim3(16, 4, 1);
        cfg.blockDim = dim3(512, 1, 1);
        cfg.dynamicSmemBytes = 0;
        cfg.stream = 0;
        cudaLaunchAttribute attrs[1];
        attrs[0].id = cudaLaunchAttributeClusterDimension;
        attrs[0].val.clusterDim = {16, 1, 1};
        cfg.attrs = attrs;
        cfg.numAttrs = 1;
        if (cudaLaunchKernelEx(&cfg, fused16, x, rw, rd, fw, fb,
                               d1w, d1b, d2w, d2b, aiw, aib, aow, aob,
                               spw, spb, ow, ob, out) == cudaSuccess)
            return;
        cudaGetLastError();  // clear and fall through to fallback
    }

    fused8<<<dim3(8, 4), 1024>>>(x, rw, rd, fw, fb, d1w, d1b, d2w, d2b,
                                 aiw, aib, aow, aob, spw, spb, ow, ob, out);
}